// round 9
// baseline (speedup 1.0000x reference)
#include <cuda_runtime.h>

#define BB 2
#define SS 2048
#define DD 128
#define HH 8
#define EPSF 1e-10f
#define FULLM 0xffffffffu
#define TTBLK 64                 // phase-1 blocks (4096 rows, 8 thr/row, 512 thr/blk)
#define NPAIR (BB * HH * SS / 2) // 16384 complementary row pairs
#define QROW  (SS / 4)           // 512 float4 per row
#define PPB   4                  // pairs per prefix block

// Scratch (allocation-free rule: __device__ globals; zero-init at load)
__device__ int      g_tt[BB * SS];
__device__ int2     g_lohi[BB * SS];
__device__ unsigned g_cnt = 0;

// ---------------------------------------------------------------------------
// Kernel 1: phase-1 only (grid 64). tt argmax + suffix-min scan -> g_lohi.
// ---------------------------------------------------------------------------
__global__ void __launch_bounds__(512) k_phase1(const float* __restrict__ x,
                                                const float* __restrict__ gu,
                                                const float* __restrict__ W,
                                                const float* __restrict__ bias) {
    const int tid = threadIdx.x;
    const int bid = blockIdx.x;

    __shared__ int sh_last;
    __shared__ int sh_wmin[16];
    __shared__ int sh_wsuf[16];

    {
        int gid = bid * 512 + tid;
        int row = gid >> 3;              // 0..4095 = b*S + s
        int r   = gid & 7;

        const float4* xr = reinterpret_cast<const float4*>(x + (size_t)row * DD);
        const float4* W4 = reinterpret_cast<const float4*>(W);

        float4 xv[4];
        #pragma unroll
        for (int i = 0; i < 4; i++) xv[i] = xr[r * 4 + i];

        float a0 = 0.f, a1 = 0.f, a2 = 0.f;
        #pragma unroll
        for (int i = 0; i < 4; i++) {
            int cc = r * 4 + i;
            float4 w0 = W4[cc];
            float4 w1 = W4[32 + cc];
            float4 w2 = W4[64 + cc];
            a0 += xv[i].x * w0.x + xv[i].y * w0.y + xv[i].z * w0.z + xv[i].w * w0.w;
            a1 += xv[i].x * w1.x + xv[i].y * w1.y + xv[i].z * w1.z + xv[i].w * w1.w;
            a2 += xv[i].x * w2.x + xv[i].y * w2.y + xv[i].z * w2.z + xv[i].w * w2.w;
        }
        #pragma unroll
        for (int off = 4; off; off >>= 1) {
            a0 += __shfl_xor_sync(FULLM, a0, off);
            a1 += __shfl_xor_sync(FULLM, a1, off);
            a2 += __shfl_xor_sync(FULLM, a2, off);
        }
        if (r == 0) {
            const float* gr = gu + (size_t)row * 3;
            float g0 = -logf(-logf(gr[0] + EPSF) + EPSF);
            float g1 = -logf(-logf(gr[1] + EPSF) + EPSF);
            float g2 = -logf(-logf(gr[2] + EPSF) + EPSF);
            float s0 = a0 + bias[0] + g0;
            float s1 = a1 + bias[1] + g1;
            float s2 = a2 + bias[2] + g2;
            int tt = 0; float best = s0;
            if (s1 > best) { best = s1; tt = 1; }   // first-max tie-break
            if (s2 > best) { best = s2; tt = 2; }
            g_tt[row] = tt;
        }
    }
    __syncthreads();
    if (tid == 0) {
        __threadfence();                              // release g_tt
        sh_last = (atomicAdd(&g_cnt, 1u) == TTBLK - 1);
    }
    __syncthreads();
    if (!sh_last) return;

    // ---------------- last block: suffix-min scan, publish (lo,hi) ----------
    __threadfence();                                  // acquire all g_tt
    int lane = tid & 31, wid = tid >> 5;              // 16 warps
    for (int b = 0; b < BB; b++) {
        __syncthreads();                              // shared reuse guard
        int base = b * SS + tid * 4;                  // 4 elems/thread
        int t0 = g_tt[base + 0], t1 = g_tt[base + 1];
        int t2 = g_tt[base + 2], t3 = g_tt[base + 3];
        int j0 = tid * 4;
        int e0 = (t0 == 0) ? j0     : SS;
        int e1 = (t1 == 0) ? j0 + 1 : SS;
        int e2 = (t2 == 0) ? j0 + 2 : SS;
        int e3 = (t3 == 0) ? j0 + 3 : SS;
        int m  = min(min(e0, e1), min(e2, e3));

        int inc = m;                                  // warp suffix-min (inclusive)
        #pragma unroll
        for (int off = 1; off < 32; off <<= 1) {
            int v = __shfl_down_sync(FULLM, inc, off);
            if (lane + off < 32) inc = min(inc, v);
        }
        int excl = __shfl_down_sync(FULLM, inc, 1);
        if (lane == 31) excl = SS;

        if (lane == 0) sh_wmin[wid] = inc;
        __syncthreads();
        if (wid == 0) {
            int wm = (lane < 16) ? sh_wmin[lane] : SS;
            int winc = wm;
            #pragma unroll
            for (int off = 1; off < 16; off <<= 1)
                winc = min(winc, __shfl_down_sync(FULLM, winc, off));
            int wex = __shfl_down_sync(FULLM, winc, 1);  // lane15 gets lane16's SS
            if (lane < 16) sh_wsuf[lane] = wex;
        }
        __syncthreads();
        int after = min(excl, sh_wsuf[wid]);          // min over idx > 4t+3

        int run = after;
        int ng3 = run; run = min(run, e3);
        int ng2 = run; run = min(run, e2);
        int ng1 = run; run = min(run, e1);
        int ng0 = run;

        int2 lh;
        #define EMIT(ii, tt_, ng_)                                  \
            { int j = j0 + ii; lh.x = 0; lh.y = j;                  \
              if (tt_ == 1)      { lh.x = j; lh.y = j; }            \
              else if (tt_ == 2) { lh.y = min(j, ng_); }            \
              g_lohi[base + ii] = lh; }
        EMIT(0, t0, ng0); EMIT(1, t1, ng1);
        EMIT(2, t2, ng2); EMIT(3, t3, ng3);
        #undef EMIT
    }
    __syncthreads();
    if (tid == 0) g_cnt = 0;            // reset for next graph replay
}

// ---------------------------------------------------------------------------
// Kernel 2 (side stream): suffix zeros for one complementary row pair.
// Exactly 511 float4 per block, constant stores. Independent of phase-1.
// ---------------------------------------------------------------------------
__global__ void __launch_bounds__(512) k_zeros(float4* __restrict__ out) {
    int zb = blockIdx.x;             // 0..16383
    int bh = zb >> 10;               // (b*8 + h)
    int a  = zb & 1023;              // s1 = a, s2 = 2047 - a
    int c  = a >> 2;                 // qdiag of row1; qdiag2 = 511 - c
    size_t base1 = (size_t)(bh * SS + a)        * QROW;
    size_t base2 = (size_t)(bh * SS + (SS-1-a)) * QROW;
    float4 z = make_float4(0.f, 0.f, 0.f, 0.f);
    int nz1 = 511 - c;               // zero float4s in row1
    int tid = threadIdx.x;
    if (tid < 511) {
        if (tid < nz1) __stcs(&out[base1 + c + 1 + tid], z);
        else           __stcs(&out[base2 + tid + 1], z);
    }
}

// ---------------------------------------------------------------------------
// Branchless quad store: element j in [lo,hi] (hi >= lo >= 0 always).
// ---------------------------------------------------------------------------
__device__ __forceinline__ void stq(float4* p, int q, int2 lh) {
    int j = q << 2;
    unsigned range = (unsigned)(lh.y - lh.x);
    float4 v;
    v.x = ((unsigned)(j     - lh.x) <= range) ? 1.f : 0.f;
    v.y = ((unsigned)(j + 1 - lh.x) <= range) ? 1.f : 0.f;
    v.z = ((unsigned)(j + 2 - lh.x) <= range) ? 1.f : 0.f;
    v.w = ((unsigned)(j + 3 - lh.x) <= range) ? 1.f : 0.f;
    __stcs(p, v);
}

// ---------------------------------------------------------------------------
// Kernel 3: causal prefixes, PPB pairs per block. All lohi loads issued
// up-front (MLP=PPB), then PPB independent stores per thread.
// w in [0,c] -> row1 q=w ; w in (c,512] -> row2 q=w-c-1 (tid0 also does w=512).
// ---------------------------------------------------------------------------
__global__ void __launch_bounds__(512) k_prefix4(float4* __restrict__ out) {
    int tid = threadIdx.x;
    int pb0 = blockIdx.x * PPB;

    int2   lh[PPB];
    size_t ad[PPB];
    int    qq[PPB];
    #pragma unroll
    for (int p = 0; p < PPB; p++) {
        int pb = pb0 + p;
        int bh = pb >> 10;
        int a  = pb & 1023;
        int b  = bh >> 3;
        int c  = a >> 2;
        int s2 = SS - 1 - a;
        bool r1  = (tid <= c);
        int srow = r1 ? a : s2;
        int q    = r1 ? tid : tid - c - 1;
        lh[p] = g_lohi[b * SS + srow];       // independent loads, MLP=PPB
        ad[p] = (size_t)(bh * SS + srow) * QROW + q;
        qq[p] = q;
    }
    #pragma unroll
    for (int p = 0; p < PPB; p++) stq(&out[ad[p]], qq[p], lh[p]);

    if (tid == 0) {                          // w=512: row2 diagonal quad
        #pragma unroll
        for (int p = 0; p < PPB; p++) {
            int pb = pb0 + p;
            int bh = pb >> 10;
            int a  = pb & 1023;
            int b  = bh >> 3;
            int c  = a >> 2;
            int s2 = SS - 1 - a;
            int q  = 511 - c;
            int2 l2 = g_lohi[b * SS + s2];
            stq(&out[(size_t)(bh * SS + s2) * QROW + q], q, l2);
        }
    }
}

// ---------------------------------------------------------------------------
// Launch: fork-join. Side stream writes zeros concurrently with phase-1 and
// the prefix writer. Handles created once on first (non-captured) call.
// ---------------------------------------------------------------------------
extern "C" void kernel_launch(void* const* d_in, const int* in_sizes, int n_in,
                              void* d_out, int out_size) {
    const float* x    = (const float*)d_in[0];  // input_tensor (B,S,D)
    // d_in[1] = token_types (unused by reference)
    const float* gu   = (const float*)d_in[2];  // gumbel_u (B,S,3)
    const float* W    = (const float*)d_in[3];  // (3,D)
    const float* bias = (const float*)d_in[4];  // (3,)
    float4* out = (float4*)d_out;

    static cudaStream_t s2 = nullptr;
    static cudaEvent_t  evFork = nullptr, evJoin = nullptr;
    if (s2 == nullptr) {                       // first call precedes capture
        cudaStreamCreateWithFlags(&s2, cudaStreamNonBlocking);
        cudaEventCreateWithFlags(&evFork, cudaEventDisableTiming);
        cudaEventCreateWithFlags(&evJoin, cudaEventDisableTiming);
    }

    // Fork: side stream inherits capture via event wait.
    cudaEventRecord(evFork, 0);
    cudaStreamWaitEvent(s2, evFork, 0);

    k_zeros<<<NPAIR, 512, 0, s2>>>(out);                 // 134 MB, no deps

    k_phase1<<<TTBLK, 512>>>(x, gu, W, bias);            // ~6 us, low BW
    k_prefix4<<<NPAIR / PPB, 512>>>(out);                // 134 MB, after phase-1

    // Join: main stream waits for side stream before returning.
    cudaEventRecord(evJoin, s2);
    cudaStreamWaitEvent(0, evJoin, 0);
}